// round 2
// baseline (speedup 1.0000x reference)
#include <cuda_runtime.h>

// Round-to-nearest-even magic constant (1.5 * 2^23), valid for |y| < 2^22.
#define RMAGIC 12582912.0f
#define NLEV_M1 255.0f

// Bin table: linear bins over |x| * BSCALE, clamped to NB-1.
#define NB     4096
#define BSCALE 1020.0f
#define F_INF  __int_as_float(0x7f800000)

// Device-global scratch (no allocations allowed).
__device__ float2 g_bins[NB];   // {split, __int_as_float(g0)}
__device__ float4 g_lut[16];    // {1/d, d, -zp, 255-zp}; index clamped via duplication
__device__ int    g_flag;       // 1 -> some bin has >=2 ambiguous medians -> fallback

// -------------------------------------------------------------------------
// Build kernel: one block. For each bin, classify every median as
// definitely-below / definitely-above / ambiguous w.r.t. the bin's preimage
// under idx = min((int)(|x|*BSCALE), NB-1), with conservative rounding slop.
// -------------------------------------------------------------------------
__global__ void build_table_kernel(const float* __restrict__ med,
                                   const float* __restrict__ del,
                                   const float* __restrict__ zp, int G)
{
    __shared__ float sm[64];
    int t = threadIdx.x;
    for (int k = t; k < G; k += blockDim.x) sm[k] = med[k];
    if (t == 0) g_flag = 0;
    if (t < 16) {
        int g = (t < G) ? t : (G - 1);
        float d = del[g];
        float z = zp[g];
        g_lut[t] = make_float4(__frcp_rn(d), d, -z, NLEV_M1 - z);
    }
    __syncthreads();

    for (int i = t; i < NB; i += blockDim.x) {
        float lo = (float)i / BSCALE;
        float hi = (float)(i + 1) / BSCALE;
        // conservative preimage bounds (cover fp rounding in both maps)
        float lo_s = lo - fabsf(lo) * 6e-7f - 1e-30f;
        float hi_s = (i == NB - 1) ? F_INF : (hi + hi * 6e-7f);

        int g0 = 0, namb = 0;
        float s1 = F_INF;
        for (int k = 0; k < G; k++) {
            float m = sm[k];
            if (m <= lo_s) {
                g0++;                       // all |x| in bin >= m
            } else if (m <= hi_s) {
                if (namb == 0) s1 = m;      // needs a runtime compare
                namb++;
            }                               // else: all |x| in bin < m
        }
        if (namb > 1) g_flag = 1;           // benign race; any 1 wins
        g_bins[i] = make_float2(s1, __int_as_float(g0));
    }
}

// -------------------------------------------------------------------------
// Per-element math.
// -------------------------------------------------------------------------
__device__ __forceinline__ float q_core(float xv, float4 L)
{
    float y = xv * L.x;                 // x * (1/d)
    float r = __fmaf_rn(y, -L.y, xv);   // residual x - y*d
    y = __fmaf_rn(r, L.x, y);           // refined quotient (matches true x/d)
    float tt = __fadd_rn(y, RMAGIC);    // round-to-nearest-even
    tt = __fadd_rn(tt, -RMAGIC);
    tt = fminf(fmaxf(tt, L.z), L.w);    // clip(round, -zp, 255-zp)
    return tt * L.y;                    // * d
}

__device__ __forceinline__ float q1_fast(float xv,
                                         const float2* __restrict__ sb,
                                         const float4* __restrict__ lut)
{
    float xa = fabsf(xv);
    int idx = __float2int_rz(xa * BSCALE);
    idx = min(idx, NB - 1);
    float2 b = sb[idx];
    int c = __float_as_int(b.y) + ((xa >= b.x) ? 1 : 0);
    return q_core(xv, lut[c]);
}

template <int G>
__device__ __forceinline__ float q1_slow(float xv,
                                         const float* __restrict__ m,
                                         const float4* __restrict__ lut)
{
    float xa = fabsf(xv);
    int c = 0;
#pragma unroll
    for (int k = 0; k < G; k++) c += (xa >= m[k]) ? 1 : 0;
    return q_core(xv, lut[c]);
}

__device__ __forceinline__ float4 q4_fast(float4 v, const float2* __restrict__ sb,
                                          const float4* __restrict__ lut)
{
    float4 o;
    o.x = q1_fast(v.x, sb, lut);
    o.y = q1_fast(v.y, sb, lut);
    o.z = q1_fast(v.z, sb, lut);
    o.w = q1_fast(v.w, sb, lut);
    return o;
}

template <int G>
__device__ __forceinline__ float4 q4_slow(float4 v, const float* __restrict__ m,
                                          const float4* __restrict__ lut)
{
    float4 o;
    o.x = q1_slow<G>(v.x, m, lut);
    o.y = q1_slow<G>(v.y, m, lut);
    o.z = q1_slow<G>(v.z, m, lut);
    o.w = q1_slow<G>(v.w, m, lut);
    return o;
}

// -------------------------------------------------------------------------
// Main vectorized kernel.
// -------------------------------------------------------------------------
template <int G>
__global__ void __launch_bounds__(256, 6) quant_vec_kernel(
    const float4* __restrict__ x,
    const float* __restrict__ med,
    float4* __restrict__ out,
    int n4)
{
    __shared__ float2 sbins[NB];
    __shared__ float4 slut[16];
    __shared__ float  smed[G];

    for (int i = threadIdx.x; i < NB / 2; i += 256)
        ((float4*)sbins)[i] = ((const float4*)g_bins)[i];
    if (threadIdx.x < 16) slut[threadIdx.x] = g_lut[threadIdx.x];
    if (threadIdx.x < G) smed[threadIdx.x] = med[threadIdx.x];
    int flag = g_flag;
    __syncthreads();

    const int stride = gridDim.x * blockDim.x;
    const int i0 = blockIdx.x * blockDim.x + threadIdx.x;
    const int per = stride * 4;
    const int nmain = (n4 / per) * per;

    if (!flag) {
        for (int i = i0; i < nmain; i += per) {
            float4 v0 = __ldg(x + i);
            float4 v1 = __ldg(x + i + stride);
            float4 v2 = __ldg(x + i + 2 * stride);
            float4 v3 = __ldg(x + i + 3 * stride);
            out[i]              = q4_fast(v0, sbins, slut);
            out[i + stride]     = q4_fast(v1, sbins, slut);
            out[i + 2 * stride] = q4_fast(v2, sbins, slut);
            out[i + 3 * stride] = q4_fast(v3, sbins, slut);
        }
        for (int i = nmain + i0; i < n4; i += stride)
            out[i] = q4_fast(__ldg(x + i), sbins, slut);
    } else {
        for (int i = i0; i < nmain; i += per) {
            float4 v0 = __ldg(x + i);
            float4 v1 = __ldg(x + i + stride);
            float4 v2 = __ldg(x + i + 2 * stride);
            float4 v3 = __ldg(x + i + 3 * stride);
            out[i]              = q4_slow<G>(v0, smed, slut);
            out[i + stride]     = q4_slow<G>(v1, smed, slut);
            out[i + 2 * stride] = q4_slow<G>(v2, smed, slut);
            out[i + 3 * stride] = q4_slow<G>(v3, smed, slut);
        }
        for (int i = nmain + i0; i < n4; i += stride)
            out[i] = q4_slow<G>(__ldg(x + i), smed, slut);
    }
}

// -------------------------------------------------------------------------
// Generic scalar fallback (runtime G, and n%4 tail).
// -------------------------------------------------------------------------
__global__ void quant_scalar_kernel(
    const float* __restrict__ x,
    const float* __restrict__ med,
    const float* __restrict__ del,
    const float* __restrict__ zp,
    float* __restrict__ out,
    int n, int G, int start)
{
    __shared__ float smed[128];
    __shared__ float4 slut[129];
    for (int t = threadIdx.x; t < G; t += blockDim.x) smed[t] = med[t];
    for (int t = threadIdx.x; t < G + 1; t += blockDim.x) {
        int g = (t < G) ? t : (G - 1);
        float d = del[g];
        float z = zp[g];
        slut[t] = make_float4(__frcp_rn(d), d, -z, NLEV_M1 - z);
    }
    __syncthreads();

    const int stride = gridDim.x * blockDim.x;
    for (int i = start + blockIdx.x * blockDim.x + threadIdx.x; i < n; i += stride) {
        float xv = x[i];
        float xa = fabsf(xv);
        int c = 0;
        for (int k = 0; k < G; k++) c += (xa >= smed[k]) ? 1 : 0;
        float4 L = slut[c];
        out[i] = q_core(xv, L);
    }
}

// -------------------------------------------------------------------------
// Launch
// -------------------------------------------------------------------------
extern "C" void kernel_launch(void* const* d_in, const int* in_sizes, int n_in,
                              void* d_out, int out_size)
{
    const float* x   = (const float*)d_in[0];
    const float* med = (const float*)d_in[1];
    const float* del = (const float*)d_in[2];
    const float* zp  = (const float*)d_in[3];
    float* out = (float*)d_out;

    const int n = in_sizes[0];
    const int G = in_sizes[1];

    if (G == 10) {
        build_table_kernel<<<1, 256>>>(med, del, zp, G);
        const int n4 = n / 4;
        if (n4 > 0) {
            int blocks = 2048;
            int maxb = (n4 + 1023) / 1024;
            if (blocks > maxb) blocks = maxb;
            quant_vec_kernel<10><<<blocks, 256>>>(
                (const float4*)x, med, (float4*)out, n4);
        }
        const int rem_start = (n / 4) * 4;
        if (rem_start < n) {
            quant_scalar_kernel<<<1, 256>>>(x, med, del, zp, out, n, G, rem_start);
        }
    } else {
        int blocks = (n + 255) / 256;
        if (blocks > 8192) blocks = 8192;
        if (blocks < 1) blocks = 1;
        quant_scalar_kernel<<<blocks, 256>>>(x, med, del, zp, out, n, G, 0);
    }
}

// round 3
// speedup vs baseline: 1.0846x; 1.0846x over previous
#include <cuda_runtime.h>

// Round-to-nearest-even magic constant (1.5 * 2^23), valid for |y| < 2^22.
#define RMAGIC 12582912.0f
#define NLEV_M1 255.0f
#define F_INF  __int_as_float(0x7f800000)

// Bit-space bin table: idx = clamp((bits(|x|) - BASEB) >> SHIFTB, 0, NBB-1)
// Exact: bin i covers float values [as_float(BASEB + i*2^SHIFTB),
//                                   as_float(BASEB + (i+1)*2^SHIFTB) )
#define NBB    4096
#define BASEB  0x3F000000u            // bits(0.5f)
#define SHIFTB 13                     // bin = 2^13 ulps (~1/1024 octave)

// Device-global scratch (no allocations allowed).
__device__ float2 g_bins[NBB];  // {split (median or +INF), as_float(g0)}
__device__ float4 g_lut[16];    // {1/d, d, -zp, 255-zp} per group (dup past G-1)
__device__ int    g_flag;       // 1 -> >=2 ambiguous medians in one bin -> fallback

// -------------------------------------------------------------------------
// Build kernel (one block). Classification is EXACT: bin bounds are exact
// float bit patterns; a median is ambiguous only if strictly inside a bin.
// Uses only the first G-1 medians (clip(sum_{i<G},0,G-1) == sum_{i<G-1}).
// -------------------------------------------------------------------------
__global__ void build_table_kernel(const float* __restrict__ med,
                                   const float* __restrict__ del,
                                   const float* __restrict__ zp, int G)
{
    __shared__ float sm[64];
    int t = threadIdx.x;
    int Gm = G - 1;                         // effective medians
    for (int k = t; k < Gm; k += blockDim.x) sm[k] = med[k];
    if (t == 0) g_flag = 0;
    if (t < 16) {
        int g = (t < G) ? t : (G - 1);
        float d = del[g];
        float z = zp[g];
        g_lut[t] = make_float4(__frcp_rn(d), d, -z, NLEV_M1 - z);
    }
    __syncthreads();

    for (int i = t; i < NBB; i += blockDim.x) {
        unsigned lob = BASEB + ((unsigned)i << SHIFTB);
        float lo = (i == 0) ? 0.0f : __uint_as_float(lob);      // bin 0 absorbs [0, 0.5)
        float hi = (i == NBB - 1) ? F_INF
                                  : __uint_as_float(lob + (1u << SHIFTB));
        int g0 = 0, namb = 0;
        float s1 = F_INF;
        for (int k = 0; k < Gm; k++) {
            float m = sm[k];
            if (m <= lo) {
                g0++;                        // always true in this bin
            } else if (m < hi) {
                if (namb == 0) s1 = m;       // needs runtime compare
                namb++;
            }                                // else always false
        }
        if (namb > 1) g_flag = 1;            // benign race
        g_bins[i] = make_float2(s1, __int_as_float(g0));
    }
}

// -------------------------------------------------------------------------
// Per-element math.
// -------------------------------------------------------------------------
__device__ __forceinline__ float q_core(float xv, float Lx, float Ly,
                                        float Lz, float Lw)
{
    float y = xv * Lx;                  // x * (1/d)
    float r = __fmaf_rn(y, -Ly, xv);    // residual x - y*d
    y = __fmaf_rn(r, Lx, y);            // refined quotient (matches true x/d)
    float tt = __fadd_rn(y, RMAGIC);    // round-to-nearest-even
    tt = __fadd_rn(tt, -RMAGIC);
    tt = fminf(fmaxf(tt, Lz), Lw);      // clip(round, -zp, 255-zp)
    return tt * Ly;                     // * d
}

// Fast path: bin lookup (LDS.64) + LUT via warp shuffle (no smem).
__device__ __forceinline__ float q1_fast(float xv, const float2* __restrict__ sb,
                                         float lx, float ly, float lz, float lw)
{
    unsigned ab = __float_as_uint(xv) & 0x7fffffffu;
    int t = (int)ab - (int)BASEB;
    t = max(t, 0);
    int idx = min(t >> SHIFTB, NBB - 1);
    float2 b = sb[idx];
    float xa = __uint_as_float(ab);
    int c = __float_as_int(b.y) + ((xa >= b.x) ? 1 : 0);
    float Lx = __shfl_sync(0xffffffffu, lx, c);
    float Ly = __shfl_sync(0xffffffffu, ly, c);
    float Lz = __shfl_sync(0xffffffffu, lz, c);
    float Lw = __shfl_sync(0xffffffffu, lw, c);
    return q_core(xv, Lx, Ly, Lz, Lw);
}

// Slow path (only if g_flag): 9 register compares + shuffle LUT.
template <int GM>
__device__ __forceinline__ float q1_slow(float xv, const float* __restrict__ m,
                                         float lx, float ly, float lz, float lw)
{
    float xa = fabsf(xv);
    int c = 0;
#pragma unroll
    for (int k = 0; k < GM; k++) c += (xa >= m[k]) ? 1 : 0;
    float Lx = __shfl_sync(0xffffffffu, lx, c);
    float Ly = __shfl_sync(0xffffffffu, ly, c);
    float Lz = __shfl_sync(0xffffffffu, lz, c);
    float Lw = __shfl_sync(0xffffffffu, lw, c);
    return q_core(xv, Lx, Ly, Lz, Lw);
}

__device__ __forceinline__ float4 q4_fast(float4 v, const float2* __restrict__ sb,
                                          float lx, float ly, float lz, float lw)
{
    float4 o;
    o.x = q1_fast(v.x, sb, lx, ly, lz, lw);
    o.y = q1_fast(v.y, sb, lx, ly, lz, lw);
    o.z = q1_fast(v.z, sb, lx, ly, lz, lw);
    o.w = q1_fast(v.w, sb, lx, ly, lz, lw);
    return o;
}

template <int GM>
__device__ __forceinline__ float4 q4_slow(float4 v, const float* __restrict__ m,
                                          float lx, float ly, float lz, float lw)
{
    float4 o;
    o.x = q1_slow<GM>(v.x, m, lx, ly, lz, lw);
    o.y = q1_slow<GM>(v.y, m, lx, ly, lz, lw);
    o.z = q1_slow<GM>(v.z, m, lx, ly, lz, lw);
    o.w = q1_slow<GM>(v.w, m, lx, ly, lz, lw);
    return o;
}

// -------------------------------------------------------------------------
// Main vectorized kernel (G==10 path; GM = 9 medians).
// -------------------------------------------------------------------------
template <int GM>
__global__ void __launch_bounds__(256, 6) quant_vec_kernel(
    const float4* __restrict__ x,
    const float* __restrict__ med,
    float4* __restrict__ out,
    int n4)
{
    __shared__ float2 sbins[NBB];

    const int lane = threadIdx.x & 31;
    // Lane c holds the group-c LUT tuple in registers (dup past GM).
    float4 Lr = g_lut[(lane <= GM) ? lane : GM];
    float lx = Lr.x, ly = Lr.y, lz = Lr.z, lw = Lr.w;
    // Medians in registers for the (rare) fallback path.
    float mreg[GM];
#pragma unroll
    for (int k = 0; k < GM; k++) mreg[k] = __ldg(med + k);

    for (int i = threadIdx.x; i < NBB / 2; i += 256)
        ((float4*)sbins)[i] = ((const float4*)g_bins)[i];
    int flag = g_flag;
    __syncthreads();

    const int stride = gridDim.x * blockDim.x;
    const int i0 = blockIdx.x * blockDim.x + threadIdx.x;
    const int per = stride * 4;
    const int nmain = (n4 / per) * per;

    if (!flag) {
        for (int i = i0; i < nmain; i += per) {
            float4 v0 = __ldg(x + i);
            float4 v1 = __ldg(x + i + stride);
            float4 v2 = __ldg(x + i + 2 * stride);
            float4 v3 = __ldg(x + i + 3 * stride);
            out[i]              = q4_fast(v0, sbins, lx, ly, lz, lw);
            out[i + stride]     = q4_fast(v1, sbins, lx, ly, lz, lw);
            out[i + 2 * stride] = q4_fast(v2, sbins, lx, ly, lz, lw);
            out[i + 3 * stride] = q4_fast(v3, sbins, lx, ly, lz, lw);
        }
        for (int i = nmain + i0; i < n4; i += stride)
            out[i] = q4_fast(__ldg(x + i), sbins, lx, ly, lz, lw);
    } else {
        for (int i = i0; i < nmain; i += per) {
            float4 v0 = __ldg(x + i);
            float4 v1 = __ldg(x + i + stride);
            float4 v2 = __ldg(x + i + 2 * stride);
            float4 v3 = __ldg(x + i + 3 * stride);
            out[i]              = q4_slow<GM>(v0, mreg, lx, ly, lz, lw);
            out[i + stride]     = q4_slow<GM>(v1, mreg, lx, ly, lz, lw);
            out[i + 2 * stride] = q4_slow<GM>(v2, mreg, lx, ly, lz, lw);
            out[i + 3 * stride] = q4_slow<GM>(v3, mreg, lx, ly, lz, lw);
        }
        for (int i = nmain + i0; i < n4; i += stride)
            out[i] = q4_slow<GM>(__ldg(x + i), mreg, lx, ly, lz, lw);
    }
}

// -------------------------------------------------------------------------
// Generic scalar fallback (runtime G, and n%4 tail).
// -------------------------------------------------------------------------
__global__ void quant_scalar_kernel(
    const float* __restrict__ x,
    const float* __restrict__ med,
    const float* __restrict__ del,
    const float* __restrict__ zp,
    float* __restrict__ out,
    int n, int G, int start)
{
    __shared__ float smed[128];
    __shared__ float4 slut[129];
    for (int t = threadIdx.x; t < G; t += blockDim.x) smed[t] = med[t];
    for (int t = threadIdx.x; t < G + 1; t += blockDim.x) {
        int g = (t < G) ? t : (G - 1);
        float d = del[g];
        float z = zp[g];
        slut[t] = make_float4(__frcp_rn(d), d, -z, NLEV_M1 - z);
    }
    __syncthreads();

    const int stride = gridDim.x * blockDim.x;
    for (int i = start + blockIdx.x * blockDim.x + threadIdx.x; i < n; i += stride) {
        float xv = x[i];
        float xa = fabsf(xv);
        int c = 0;
        for (int k = 0; k < G; k++) c += (xa >= smed[k]) ? 1 : 0;
        if (c > G - 1) c = G - 1;
        float4 L = slut[c];
        out[i] = q_core(xv, L.x, L.y, L.z, L.w);
    }
}

// -------------------------------------------------------------------------
// Launch
// -------------------------------------------------------------------------
extern "C" void kernel_launch(void* const* d_in, const int* in_sizes, int n_in,
                              void* d_out, int out_size)
{
    const float* x   = (const float*)d_in[0];
    const float* med = (const float*)d_in[1];
    const float* del = (const float*)d_in[2];
    const float* zp  = (const float*)d_in[3];
    float* out = (float*)d_out;

    const int n = in_sizes[0];
    const int G = in_sizes[1];

    if (G == 10) {
        build_table_kernel<<<1, 256>>>(med, del, zp, G);
        const int n4 = n / 4;
        if (n4 > 0) {
            int blocks = 4096;
            int maxb = (n4 + 255) / 256;
            if (blocks > maxb) blocks = maxb;
            quant_vec_kernel<9><<<blocks, 256>>>(
                (const float4*)x, med, (float4*)out, n4);
        }
        const int rem_start = (n / 4) * 4;
        if (rem_start < n) {
            quant_scalar_kernel<<<1, 256>>>(x, med, del, zp, out, n, G, rem_start);
        }
    } else {
        int blocks = (n + 255) / 256;
        if (blocks > 8192) blocks = 8192;
        if (blocks < 1) blocks = 1;
        quant_scalar_kernel<<<blocks, 256>>>(x, med, del, zp, out, n, G, 0);
    }
}

// round 4
// speedup vs baseline: 1.1220x; 1.0345x over previous
#include <cuda_runtime.h>

// Round-to-nearest-even magic constant (1.5 * 2^23), valid for |y| < 2^22.
#define RMAGIC 12582912.0f
#define NLEV_M1 255.0f

// Bit-space bins over xk = bits(|x|) - (bits(0.5f)-1), clamped below at 0.
// Bin i covers xk in [i<<SHB, (i+1)<<SHB); last bin absorbs everything above.
#define NBB   380
#define SHB   16
#define B2    0x3EFFFFFF            // bits(0.5f) - 1
#define SPLIT_MASK 0x03FFFFFFu
#define NO_SPLIT   0x03FFFFFFu      // > any real split and > any in-range xk

// Device-global scratch (no allocations allowed).
__device__ unsigned g_packed[NBB];  // (g0 << 26) | split_xk
__device__ float4   g_lut[16];      // {1/d, d, -zp, 255-zp}; dup past G-1 up to 15
__device__ int      g_flag;         // 1 -> >=2 ambiguous medians in a bin -> fallback

// -------------------------------------------------------------------------
// Build kernel (one block). Exact classification in integer bit space.
// Uses only the first G-1 medians (clip(sum_{i<G},0,G-1) == sum_{i<G-1}).
// -------------------------------------------------------------------------
__global__ void build_table_kernel(const float* __restrict__ med,
                                   const float* __restrict__ del,
                                   const float* __restrict__ zp, int G)
{
    __shared__ int sxk[64];
    int t = threadIdx.x;
    int Gm = G - 1;
    for (int k = t; k < Gm; k += blockDim.x)
        sxk[k] = (int)__float_as_uint(med[k]) - B2;   // xk(median), >=1 for m>=0.5
    if (t == 0) g_flag = 0;
    if (t < 16) {
        int g = (t < G) ? t : (G - 1);
        float d = del[g];
        float z = zp[g];
        g_lut[t] = make_float4(__frcp_rn(d), d, -z, NLEV_M1 - z);
    }
    __syncthreads();

    for (int i = t; i < NBB; i += blockDim.x) {
        long long lo = (long long)i << SHB;
        long long hi = (i == NBB - 1) ? 0x7fffffffLL : ((long long)(i + 1) << SHB);
        int g0 = 0, namb = 0;
        unsigned split = NO_SPLIT;
        for (int k = 0; k < Gm; k++) {
            long long xm = sxk[k];
            if (xm <= lo) {
                g0++;                          // always true within this bin
            } else if (xm < hi) {
                if (namb == 0) split = (unsigned)xm;   // runtime compare
                namb++;
            }
        }
        if (namb > 1) g_flag = 1;              // benign race
        g_packed[i] = ((unsigned)g0 << 26) | split;
    }
}

// -------------------------------------------------------------------------
// Per-element math core.
// -------------------------------------------------------------------------
__device__ __forceinline__ float q_core(float xv, float4 L)
{
    float y = xv * L.x;                  // x * (1/d)
    float r = __fmaf_rn(y, -L.y, xv);    // residual x - y*d
    y = __fmaf_rn(r, L.x, y);            // refined quotient (matches true x/d)
    float tt = __fadd_rn(y, RMAGIC);     // round-to-nearest-even
    tt = __fadd_rn(tt, -RMAGIC);
    tt = fminf(fmaxf(tt, L.z), L.w);     // clip(round, -zp, 255-zp)
    return tt * L.y;                     // * d
}

// Fast path: one conflict-free LDS.32 (bank-replicated table) + LDS.128 LUT.
__device__ __forceinline__ float q1_fast(float xv,
                                         const unsigned* __restrict__ tabLane,
                                         const float4* __restrict__ lut)
{
    int xk = (int)(__float_as_uint(xv) & 0x7fffffffu) - B2;
    xk = max(xk, 0);
    int idx = min(xk >> SHB, NBB - 1);
    unsigned e = tabLane[idx * 32];            // bank == lane: conflict-free
    int c = (int)(e >> 26) + (((unsigned)xk >= (e & SPLIT_MASK)) ? 1 : 0);
    return q_core(xv, lut[c]);                 // lut dup-padded: c<=15 safe
}

// Slow path (only if g_flag): 9 register compares.
template <int GM>
__device__ __forceinline__ float q1_slow(float xv, const float* __restrict__ m,
                                         const float4* __restrict__ lut)
{
    float xa = fabsf(xv);
    int c = 0;
#pragma unroll
    for (int k = 0; k < GM; k++) c += (xa >= m[k]) ? 1 : 0;
    return q_core(xv, lut[c]);
}

__device__ __forceinline__ float4 q4_fast(float4 v,
                                          const unsigned* __restrict__ tabLane,
                                          const float4* __restrict__ lut)
{
    float4 o;
    o.x = q1_fast(v.x, tabLane, lut);
    o.y = q1_fast(v.y, tabLane, lut);
    o.z = q1_fast(v.z, tabLane, lut);
    o.w = q1_fast(v.w, tabLane, lut);
    return o;
}

template <int GM>
__device__ __forceinline__ float4 q4_slow(float4 v, const float* __restrict__ m,
                                          const float4* __restrict__ lut)
{
    float4 o;
    o.x = q1_slow<GM>(v.x, m, lut);
    o.y = q1_slow<GM>(v.y, m, lut);
    o.z = q1_slow<GM>(v.z, m, lut);
    o.w = q1_slow<GM>(v.w, m, lut);
    return o;
}

// -------------------------------------------------------------------------
// Main vectorized kernel.
// -------------------------------------------------------------------------
template <int GM>
__global__ void __launch_bounds__(256, 4) quant_vec_kernel(
    const float4* __restrict__ x,
    const float* __restrict__ med,
    float4* __restrict__ out,
    int n4)
{
    __shared__ unsigned stab[NBB * 32];   // 380*32*4 = 48640 B, 32-way replicated
    __shared__ float4   slut[16];         // 256 B

    // Fill replicated table: thread handles bins tid, tid+256, ...
    for (int i = threadIdx.x; i < NBB; i += 256) {
        unsigned p = g_packed[i];
        unsigned* row = &stab[i * 32];
#pragma unroll
        for (int l = 0; l < 32; l++) row[l] = p;
    }
    if (threadIdx.x < 16) slut[threadIdx.x] = g_lut[threadIdx.x];

    // Medians in registers for the (rare) fallback path.
    float mreg[GM];
#pragma unroll
    for (int k = 0; k < GM; k++) mreg[k] = __ldg(med + k);

    int flag = g_flag;
    __syncthreads();

    const unsigned* tabLane = stab + (threadIdx.x & 31);

    const int stride = gridDim.x * blockDim.x;
    const int i0 = blockIdx.x * blockDim.x + threadIdx.x;
    const int per = stride * 4;
    const int nmain = (n4 / per) * per;

    if (!flag) {
        for (int i = i0; i < nmain; i += per) {
            float4 v0 = __ldg(x + i);
            float4 v1 = __ldg(x + i + stride);
            float4 v2 = __ldg(x + i + 2 * stride);
            float4 v3 = __ldg(x + i + 3 * stride);
            float4 r0 = q4_fast(v0, tabLane, slut);
            float4 r1 = q4_fast(v1, tabLane, slut);
            float4 r2 = q4_fast(v2, tabLane, slut);
            float4 r3 = q4_fast(v3, tabLane, slut);
            __stcs(out + i, r0);
            __stcs(out + i + stride, r1);
            __stcs(out + i + 2 * stride, r2);
            __stcs(out + i + 3 * stride, r3);
        }
        for (int i = nmain + i0; i < n4; i += stride)
            __stcs(out + i, q4_fast(__ldg(x + i), tabLane, slut));
    } else {
        for (int i = i0; i < nmain; i += per) {
            float4 v0 = __ldg(x + i);
            float4 v1 = __ldg(x + i + stride);
            float4 v2 = __ldg(x + i + 2 * stride);
            float4 v3 = __ldg(x + i + 3 * stride);
            __stcs(out + i,              q4_slow<GM>(v0, mreg, slut));
            __stcs(out + i + stride,     q4_slow<GM>(v1, mreg, slut));
            __stcs(out + i + 2 * stride, q4_slow<GM>(v2, mreg, slut));
            __stcs(out + i + 3 * stride, q4_slow<GM>(v3, mreg, slut));
        }
        for (int i = nmain + i0; i < n4; i += stride)
            __stcs(out + i, q4_slow<GM>(__ldg(x + i), mreg, slut));
    }
}

// -------------------------------------------------------------------------
// Generic scalar fallback (runtime G, and n%4 tail).
// -------------------------------------------------------------------------
__global__ void quant_scalar_kernel(
    const float* __restrict__ x,
    const float* __restrict__ med,
    const float* __restrict__ del,
    const float* __restrict__ zp,
    float* __restrict__ out,
    int n, int G, int start)
{
    __shared__ float smed[128];
    __shared__ float4 slut[129];
    for (int t = threadIdx.x; t < G; t += blockDim.x) smed[t] = med[t];
    for (int t = threadIdx.x; t < G + 1; t += blockDim.x) {
        int g = (t < G) ? t : (G - 1);
        float d = del[g];
        float z = zp[g];
        slut[t] = make_float4(__frcp_rn(d), d, -z, NLEV_M1 - z);
    }
    __syncthreads();

    const int stride = gridDim.x * blockDim.x;
    for (int i = start + blockIdx.x * blockDim.x + threadIdx.x; i < n; i += stride) {
        float xv = x[i];
        float xa = fabsf(xv);
        int c = 0;
        for (int k = 0; k < G; k++) c += (xa >= smed[k]) ? 1 : 0;
        if (c > G - 1) c = G - 1;
        out[i] = q_core(xv, slut[c]);
    }
}

// -------------------------------------------------------------------------
// Launch
// -------------------------------------------------------------------------
extern "C" void kernel_launch(void* const* d_in, const int* in_sizes, int n_in,
                              void* d_out, int out_size)
{
    const float* x   = (const float*)d_in[0];
    const float* med = (const float*)d_in[1];
    const float* del = (const float*)d_in[2];
    const float* zp  = (const float*)d_in[3];
    float* out = (float*)d_out;

    const int n = in_sizes[0];
    const int G = in_sizes[1];

    if (G == 10) {
        build_table_kernel<<<1, 256>>>(med, del, zp, G);
        const int n4 = n / 4;
        if (n4 > 0) {
            int blocks = 4096;
            int maxb = (n4 + 255) / 256;
            if (blocks > maxb) blocks = maxb;
            quant_vec_kernel<9><<<blocks, 256>>>(
                (const float4*)x, med, (float4*)out, n4);
        }
        const int rem_start = (n / 4) * 4;
        if (rem_start < n) {
            quant_scalar_kernel<<<1, 256>>>(x, med, del, zp, out, n, G, rem_start);
        }
    } else {
        int blocks = (n + 255) / 256;
        if (blocks > 8192) blocks = 8192;
        if (blocks < 1) blocks = 1;
        quant_scalar_kernel<<<blocks, 256>>>(x, med, del, zp, out, n, G, 0);
    }
}

// round 10
// speedup vs baseline: 1.4145x; 1.2607x over previous
#include <cuda_runtime.h>

// Round-to-nearest-even magic constant (1.5 * 2^23).
// t = fma(x, invd, RMAGIC); r = t - RMAGIC  ==> r = round-half-even(x*invd),
// exact for |x*invd| < 2^22 (here |x/d| < ~1e3).
#define RMAGIC 12582912.0f
#define NLEV_M1 255.0f

// -------------------------------------------------------------------------
// Core: out = clip(round(x/d), -zp, 255-zp) * d, with L = {1/d, d, -zp, 255-zp}
// -------------------------------------------------------------------------
__device__ __forceinline__ float q_core(float xv, float4 L)
{
    float t  = __fmaf_rn(xv, L.x, RMAGIC);   // x*(1/d) + magic (RNE round)
    float r  = __fadd_rn(t, -RMAGIC);        // round-half-even(x/d)
    r = fminf(fmaxf(r, L.z), L.w);           // clip(round, -zp, 255-zp)
    return r * L.y;                          // * d
}

// Group id: count of medians <= |x| over the first GM(=G-1) medians.
// (clip(sum_{i<G}, 0, G-1) == sum_{i<G-1} for sorted medians.)
template <int GM>
__device__ __forceinline__ float q1(float xv, const float* __restrict__ m,
                                    const float4* __restrict__ lut)
{
    int c = 0;
#pragma unroll
    for (int k = 0; k < GM; k++) c += (fabsf(xv) >= m[k]) ? 1 : 0;  // |x| folds into FSETP
    return q_core(xv, lut[c]);               // single LDS.128 per element
}

template <int GM>
__device__ __forceinline__ float4 q4(float4 v, const float* __restrict__ m,
                                     const float4* __restrict__ lut)
{
    float4 o;
    o.x = q1<GM>(v.x, m, lut);
    o.y = q1<GM>(v.y, m, lut);
    o.z = q1<GM>(v.z, m, lut);
    o.w = q1<GM>(v.w, m, lut);
    return o;
}

// -------------------------------------------------------------------------
// Main vectorized kernel (GM = G-1 medians in registers).
// -------------------------------------------------------------------------
template <int GM>
__global__ void __launch_bounds__(256, 4) quant_vec_kernel(
    const float4* __restrict__ x,
    const float* __restrict__ med,
    const float* __restrict__ del,
    const float* __restrict__ zp,
    float4* __restrict__ out,
    int n4)
{
    __shared__ float4 slut[GM + 1];
    if (threadIdx.x <= GM) {
        float d = del[threadIdx.x];
        float z = zp[threadIdx.x];
        slut[threadIdx.x] = make_float4(__frcp_rn(d), d, -z, NLEV_M1 - z);
    }
    __syncthreads();

    float m[GM];
#pragma unroll
    for (int k = 0; k < GM; k++) m[k] = __ldg(med + k);

    const int stride = gridDim.x * blockDim.x;
    const int i0 = blockIdx.x * blockDim.x + threadIdx.x;
    const int per = stride * 4;
    const int nmain = (n4 / per) * per;

    for (int i = i0; i < nmain; i += per) {
        float4 v0 = __ldg(x + i);
        float4 v1 = __ldg(x + i + stride);
        float4 v2 = __ldg(x + i + 2 * stride);
        float4 v3 = __ldg(x + i + 3 * stride);
        out[i]              = q4<GM>(v0, m, slut);
        out[i + stride]     = q4<GM>(v1, m, slut);
        out[i + 2 * stride] = q4<GM>(v2, m, slut);
        out[i + 3 * stride] = q4<GM>(v3, m, slut);
    }
    for (int i = nmain + i0; i < n4; i += stride)
        out[i] = q4<GM>(__ldg(x + i), m, slut);
}

// -------------------------------------------------------------------------
// Generic scalar fallback (runtime G, and n%4 tail).
// -------------------------------------------------------------------------
__global__ void quant_scalar_kernel(
    const float* __restrict__ x,
    const float* __restrict__ med,
    const float* __restrict__ del,
    const float* __restrict__ zp,
    float* __restrict__ out,
    int n, int G, int start)
{
    __shared__ float smed[128];
    __shared__ float4 slut[128];
    for (int t = threadIdx.x; t < G; t += blockDim.x) {
        smed[t] = med[t];
        float d = del[t];
        float z = zp[t];
        slut[t] = make_float4(__frcp_rn(d), d, -z, NLEV_M1 - z);
    }
    __syncthreads();

    const int stride = gridDim.x * blockDim.x;
    for (int i = start + blockIdx.x * blockDim.x + threadIdx.x; i < n; i += stride) {
        float xv = x[i];
        int c = 0;
        for (int k = 0; k < G; k++) c += (fabsf(xv) >= smed[k]) ? 1 : 0;
        if (c > G - 1) c = G - 1;
        out[i] = q_core(xv, slut[c]);
    }
}

// -------------------------------------------------------------------------
// Launch
// -------------------------------------------------------------------------
extern "C" void kernel_launch(void* const* d_in, const int* in_sizes, int n_in,
                              void* d_out, int out_size)
{
    const float* x   = (const float*)d_in[0];
    const float* med = (const float*)d_in[1];
    const float* del = (const float*)d_in[2];
    const float* zp  = (const float*)d_in[3];
    float* out = (float*)d_out;

    const int n = in_sizes[0];
    const int G = in_sizes[1];

    if (G == 10) {
        const int n4 = n / 4;
        if (n4 > 0) {
            int blocks = 4736;                 // 32 CTAs/SM-wave * 148 SMs
            int maxb = (n4 + 255) / 256;
            if (blocks > maxb) blocks = maxb;
            quant_vec_kernel<9><<<blocks, 256>>>(
                (const float4*)x, med, del, zp, (float4*)out, n4);
        }
        const int rem_start = (n / 4) * 4;
        if (rem_start < n) {
            quant_scalar_kernel<<<1, 256>>>(x, med, del, zp, out, n, G, rem_start);
        }
    } else {
        int blocks = (n + 255) / 256;
        if (blocks > 8192) blocks = 8192;
        if (blocks < 1) blocks = 1;
        quant_scalar_kernel<<<blocks, 256>>>(x, med, del, zp, out, n, G, 0);
    }
}